// round 8
// baseline (speedup 1.0000x reference)
#include <cuda_runtime.h>
#include <cuda_bf16.h>
#include <math.h>
#include <stdint.h>

#define E 128
#define H 8
#define L 2048
#define HE 1024
#define HEL (HE * L)
#define NITEMS 50000
#define WAMT 5
#define SCALE_F 0.08838834764831845f

__device__ float g_I[E * L];
__device__ __nv_bfloat16 g_Qh[H * L * E], g_Ql[H * L * E];   // [h][l][e], pre-scaled
__device__ __nv_bfloat16 g_Kh[H * L * E], g_Kl[H * L * E];   // [h][l][e]
__device__ __nv_bfloat16 g_Vh[H * E * L], g_Vl[H * E * L];   // [h][e][l]
__device__ __nv_bfloat16 g_bh[L * HE], g_bl[L * HE];         // [l][he]
__device__ __nv_bfloat16 g_Ah[E * HE], g_Al[E * HE];         // [e_out][k]

__device__ __forceinline__ uint32_t smem_u32(const void* p) {
    return (uint32_t)__cvta_generic_to_shared(p);
}
__device__ __forceinline__ void ldsm4(uint32_t* r, uint32_t a) {
    asm volatile("ldmatrix.sync.aligned.m8n8.x4.shared.b16 {%0,%1,%2,%3}, [%4];"
                 : "=r"(r[0]), "=r"(r[1]), "=r"(r[2]), "=r"(r[3]) : "r"(a));
}
__device__ __forceinline__ void ldsm4t(uint32_t* r, uint32_t a) {
    asm volatile("ldmatrix.sync.aligned.m8n8.x4.trans.shared.b16 {%0,%1,%2,%3}, [%4];"
                 : "=r"(r[0]), "=r"(r[1]), "=r"(r[2]), "=r"(r[3]) : "r"(a));
}
__device__ __forceinline__ void mma_bf16(float* c, const uint32_t* a, const uint32_t* b) {
    asm volatile("mma.sync.aligned.m16n8k16.row.col.f32.bf16.bf16.f32 "
                 "{%0,%1,%2,%3}, {%4,%5,%6,%7}, {%8,%9}, {%0,%1,%2,%3};"
                 : "+f"(c[0]), "+f"(c[1]), "+f"(c[2]), "+f"(c[3])
                 : "r"(a[0]), "r"(a[1]), "r"(a[2]), "r"(a[3]), "r"(b[0]), "r"(b[1]));
}
__device__ __forceinline__ void split2(float a, float b, __nv_bfloat162& h, __nv_bfloat162& l) {
    h = __floats2bfloat162_rn(a, b);
    float2 r = __bfloat1622float2(h);
    l = __floats2bfloat162_rn(a - r.x, b - r.y);
}

// ---------------------------------------------------------------------------
__global__ void build_I_kernel(const int* __restrict__ sq, const int* __restrict__ cq,
                               const float* __restrict__ ir, const float* __restrict__ wr,
                               const float* __restrict__ uir, float* __restrict__ out) {
    int idx = blockIdx.x * blockDim.x + threadIdx.x;
    if (idx < E) out[idx] = uir[idx];
    if (idx >= E * L) return;
    int e = idx & 127, l = idx >> 7;
    float iq = ir[e * NITEMS + sq[l]];
    g_I[e * L + l] = iq + wr[e * WAMT + cq[l]];
    out[E * L + idx] = iq;
}

__global__ void prep_A_kernel(const float* __restrict__ A) {
    int idx = blockIdx.x * blockDim.x + threadIdx.x;
    int i2 = idx * 2;
    float2 f = *(const float2*)&A[i2];
    __nv_bfloat162 hh, ll;
    split2(f.x, f.y, hh, ll);
    *(__nv_bfloat162*)&g_Ah[i2] = hh;
    *(__nv_bfloat162*)&g_Al[i2] = ll;
}

// ---------------------------------------------------------------------------
__global__ __launch_bounds__(256) void gemm_qkv_kernel(const float* __restrict__ Wq,
                                                       const float* __restrict__ Wk,
                                                       const float* __restrict__ Wv) {
    __shared__ float As[64 * 68], Bs[64 * 68];
    const float* W = (blockIdx.z == 0) ? Wq : (blockIdx.z == 1 ? Wk : Wv);
    const int bm = blockIdx.y * 64, bn = blockIdx.x * 64;
    const int t = threadIdx.x, tx = t & 15, ty = t >> 4;
    float acc[4][4];
#pragma unroll
    for (int u = 0; u < 4; u++)
#pragma unroll
        for (int v = 0; v < 4; v++) acc[u][v] = 0.f;
    for (int k0 = 0; k0 < 128; k0 += 64) {
#pragma unroll
        for (int r = 0; r < 4; ++r) {
            int id = t + r * 256, m = id >> 4, kq = id & 15;
            float4 w4 = *(const float4*)&W[(bm + m) * 128 + k0 + kq * 4];
            As[(kq * 4 + 0) * 68 + m] = w4.x; As[(kq * 4 + 1) * 68 + m] = w4.y;
            As[(kq * 4 + 2) * 68 + m] = w4.z; As[(kq * 4 + 3) * 68 + m] = w4.w;
        }
#pragma unroll
        for (int r = 0; r < 4; ++r) {
            int id = t + r * 256, k = id >> 4, n4 = (id & 15) << 2;
            *(float4*)&Bs[k * 68 + n4] = *(const float4*)&g_I[(size_t)(k0 + k) * L + bn + n4];
        }
        __syncthreads();
#pragma unroll 8
        for (int k = 0; k < 64; ++k) {
            float4 a4 = *(const float4*)&As[k * 68 + ty * 4];
            float4 b4 = *(const float4*)&Bs[k * 68 + tx * 4];
            float a[4] = {a4.x, a4.y, a4.z, a4.w}, b[4] = {b4.x, b4.y, b4.z, b4.w};
#pragma unroll
            for (int u = 0; u < 4; u++)
#pragma unroll
                for (int v = 0; v < 4; v++) acc[u][v] = fmaf(a[u], b[v], acc[u][v]);
        }
        __syncthreads();
    }
    const int m0 = bm + ty * 4;
    const int n0 = bn + tx * 4;
    const int h = m0 >> 7, e0 = m0 & 127;
    if (blockIdx.z < 2) {
        __nv_bfloat16* Dh = blockIdx.z ? g_Kh : g_Qh;
        __nv_bfloat16* Dl = blockIdx.z ? g_Kl : g_Ql;
        const float s = blockIdx.z ? 1.0f : SCALE_F;
#pragma unroll
        for (int v = 0; v < 4; ++v) {
            __nv_bfloat162 h01, l01, h23, l23;
            split2(acc[0][v] * s, acc[1][v] * s, h01, l01);
            split2(acc[2][v] * s, acc[3][v] * s, h23, l23);
            size_t base = ((size_t)h * L + n0 + v) * E + e0;
            *(__nv_bfloat162*)&Dh[base] = h01;
            *(__nv_bfloat162*)&Dh[base + 2] = h23;
            *(__nv_bfloat162*)&Dl[base] = l01;
            *(__nv_bfloat162*)&Dl[base + 2] = l23;
        }
    } else {
#pragma unroll
        for (int u = 0; u < 4; ++u) {
            __nv_bfloat162 h01, l01, h23, l23;
            split2(acc[u][0], acc[u][1], h01, l01);
            split2(acc[u][2], acc[u][3], h23, l23);
            size_t base = ((size_t)h * E + e0 + u) * L + n0;
            *(__nv_bfloat162*)&g_Vh[base] = h01;
            *(__nv_bfloat162*)&g_Vh[base + 2] = h23;
            *(__nv_bfloat162*)&g_Vl[base] = l01;
            *(__nv_bfloat162*)&g_Vl[base + 2] = l23;
        }
    }
}

// ---------------------------------------------------------------------------
// Attention: 128 threads/CTA, 32 queries/CTA, 2 CTAs/SM.
// Q [j][e] stride 136, K [i][e] stride 136, V [e][i] stride 72, P [i][j] stride 40.
// S: warp w -> 16i x 32j. PV: warp w -> 32e x 32j.
// ---------------------------------------------------------------------------
#define SQK 136
#define SV 72
#define SP 40
#define S_QH 0
#define S_QL 8704
#define S_KH 17408
#define S_KL 35072
#define S_VH 52736
#define S_VL 71168
#define S_PH 89600
#define S_PL 94720
#define S_LS 99840
#define S_RED 99968
#define ATTN_SMEM 100480

__global__ __launch_bounds__(128, 2) void attn_kernel() {
    extern __shared__ __align__(128) char smc[];
    const uint32_t sb = smem_u32(smc);
    const int t = threadIdx.x, w = t >> 5, ln = t & 31;
    const int bid = blockIdx.x;
    const int h = bid & 7;
    const int jt = 63 - (bid >> 3);         // biggest tiles first
    const int qb = jt << 5;
    const int nst = (jt >> 1) + 1;
    float* l_s = (float*)(smc + S_LS);
    float* red = (float*)(smc + S_RED);

    const __nv_bfloat16* Qh = g_Qh + (size_t)h * L * E;
    const __nv_bfloat16* Ql = g_Ql + (size_t)h * L * E;
    const __nv_bfloat16* Kh = g_Kh + (size_t)h * L * E;
    const __nv_bfloat16* Kl = g_Kl + (size_t)h * L * E;
    const __nv_bfloat16* Vh = g_Vh + (size_t)h * E * L;
    const __nv_bfloat16* Vl = g_Vl + (size_t)h * E * L;

    const int iw = w * 16;
    const int mA = ln >> 3, g8 = ln & 7;
    const int sArow = iw + g8 + (mA & 1) * 8;   // K row (i)
    const int sAcol = (mA >> 1) * 8;
    const int sBrow = g8 + (mA >> 1) * 8;       // Q row (j within 16-tile)
    const int sBcol = (mA & 1) * 8;
    const int pAcol = (mA >> 1) * 8;            // i within k16
    const int pBrow = g8 + (mA & 1) * 8;        // P row (i within k16)
    const int pBcol = (mA >> 1) * 8;            // j within 16-tile

    // Q tile copy: 32 rows x 16 chunks, hi+lo
#pragma unroll
    for (int r = 0; r < 4; ++r) {
        int id = t + r * 128, row = id >> 4, c16 = id & 15;
        *(uint4*)(smc + S_QH + row * 272 + c16 * 16) =
            *((const uint4*)(Qh + (size_t)(qb + row) * E) + c16);
        *(uint4*)(smc + S_QL + row * 272 + c16 * 16) =
            *((const uint4*)(Ql + (size_t)(qb + row) * E) + c16);
    }
    if (t < 32) l_s[t] = 0.f;

    float bacc[8][4];
#pragma unroll
    for (int u = 0; u < 8; u++)
#pragma unroll
        for (int v = 0; v < 4; v++) bacc[u][v] = 0.f;

#pragma unroll 1
    for (int ib = 0; ib < nst; ++ib) {
        __syncthreads();   // prev PV/l_s reads done; Q visible on first iter
        // K tile: 64 rows x 16 chunks
#pragma unroll
        for (int r = 0; r < 8; ++r) {
            int id = t + r * 128, row = id >> 4, c16 = id & 15;
            *(uint4*)(smc + S_KH + row * 272 + c16 * 16) =
                *((const uint4*)(Kh + (size_t)(ib * 64 + row) * E) + c16);
            *(uint4*)(smc + S_KL + row * 272 + c16 * 16) =
                *((const uint4*)(Kl + (size_t)(ib * 64 + row) * E) + c16);
        }
        // V tile: 128 rows x 8 chunks
#pragma unroll
        for (int r = 0; r < 8; ++r) {
            int id = t + r * 128, row = id >> 3, c8 = id & 7;
            *(uint4*)(smc + S_VH + row * 144 + c8 * 16) =
                *((const uint4*)(Vh + (size_t)row * L + ib * 64) + c8);
            *(uint4*)(smc + S_VL + row * 144 + c8 * 16) =
                *((const uint4*)(Vl + (size_t)row * L + ib * 64) + c8);
        }
        __syncthreads();   // K/V ready

        // ---- S = K^T Q (16i x 32j per warp), 3-term ----
        float sacc[4][4];
#pragma unroll
        for (int u = 0; u < 4; u++)
#pragma unroll
            for (int v = 0; v < 4; v++) sacc[u][v] = 0.f;
#pragma unroll
        for (int ks = 0; ks < 8; ++ks) {
            int e0 = ks * 16;
            uint32_t ah[4], al[4];
            ldsm4(ah, sb + S_KH + (uint32_t)((sArow * SQK + e0 + sAcol) * 2));
            ldsm4(al, sb + S_KL + (uint32_t)((sArow * SQK + e0 + sAcol) * 2));
#pragma unroll
            for (int np = 0; np < 2; ++np) {
                int j16 = np * 16;
                uint32_t bh[4], bl[4];
                uint32_t boff = (uint32_t)(((j16 + sBrow) * SQK + e0 + sBcol) * 2);
                ldsm4(bh, sb + S_QH + boff);
                ldsm4(bl, sb + S_QL + boff);
                mma_bf16(sacc[np * 2], ah, bh);
                mma_bf16(sacc[np * 2], ah, bl);
                mma_bf16(sacc[np * 2], al, bh);
                mma_bf16(sacc[np * 2 + 1], ah, bh + 2);
                mma_bf16(sacc[np * 2 + 1], ah, bl + 2);
                mma_bf16(sacc[np * 2 + 1], al, bh + 2);
            }
        }

        // ---- exp + causal mask + P hi/lo + column sums ----
        const int rl0 = iw + (ln >> 2);
        const int i0g = ib * 64 + rl0;
#pragma unroll
        for (int nt = 0; nt < 4; ++nt) {
            int jc = nt * 8 + (ln & 3) * 2;
            int jg = qb + jc;
            float p0 = (i0g <= jg)     ? __expf(sacc[nt][0]) : 0.f;
            float p1 = (i0g <= jg + 1) ? __expf(sacc[nt][1]) : 0.f;
            float p2 = (i0g + 8 <= jg)     ? __expf(sacc[nt][2]) : 0.f;
            float p3 = (i0g + 8 <= jg + 1) ? __expf(sacc[nt][3]) : 0.f;
            __nv_bfloat162 h01, l01, h23, l23;
            split2(p0, p1, h01, l01);
            split2(p2, p3, h23, l23);
            int o0 = (rl0 * SP + jc) * 2;
            int o1 = ((rl0 + 8) * SP + jc) * 2;
            *(__nv_bfloat162*)(smc + S_PH + o0) = h01;
            *(__nv_bfloat162*)(smc + S_PH + o1) = h23;
            *(__nv_bfloat162*)(smc + S_PL + o0) = l01;
            *(__nv_bfloat162*)(smc + S_PL + o1) = l23;
            float cs0 = p0 + p2, cs1 = p1 + p3;
#pragma unroll
            for (int off = 4; off < 32; off <<= 1) {
                cs0 += __shfl_xor_sync(0xffffffffu, cs0, off);
                cs1 += __shfl_xor_sync(0xffffffffu, cs1, off);
            }
            if (ln < 4) { red[w * 32 + jc] = cs0; red[w * 32 + jc + 1] = cs1; }
        }
        __syncthreads();   // P + red ready
        if (t < 32) l_s[t] += red[t] + red[32 + t] + red[64 + t] + red[96 + t];

        // ---- PV: 32e x 32j per warp, 3-term ----
#pragma unroll
        for (int mt = 0; mt < 2; ++mt) {
            const int pArow = w * 32 + mt * 16 + g8 + (mA & 1) * 8;
#pragma unroll
            for (int ks = 0; ks < 4; ++ks) {
                int i0 = ks * 16;
                uint32_t ah[4], al[4];
                uint32_t aoff = (uint32_t)((pArow * SV + i0 + pAcol) * 2);
                ldsm4(ah, sb + S_VH + aoff);
                ldsm4(al, sb + S_VL + aoff);
#pragma unroll
                for (int np = 0; np < 2; ++np) {
                    int j16 = np * 16;
                    uint32_t bh[4], bl[4];
                    uint32_t boff = (uint32_t)(((i0 + pBrow) * SP + j16 + pBcol) * 2);
                    ldsm4t(bh, sb + S_PH + boff);
                    ldsm4t(bl, sb + S_PL + boff);
                    float* c0 = bacc[mt * 4 + np * 2];
                    float* c1 = bacc[mt * 4 + np * 2 + 1];
                    mma_bf16(c0, ah, bh);
                    mma_bf16(c0, ah, bl);
                    mma_bf16(c0, al, bh);
                    mma_bf16(c1, ah, bh + 2);
                    mma_bf16(c1, ah, bl + 2);
                    mma_bf16(c1, al, bh + 2);
                }
            }
        }
    }
    __syncthreads();   // l_s final

    // epilogue: normalize + split + store b hi/lo at [l][he]
#pragma unroll
    for (int mt = 0; mt < 2; ++mt) {
        const int r0 = w * 32 + mt * 16 + (ln >> 2);
#pragma unroll
        for (int nf = 0; nf < 4; ++nf) {
            int jc = nf * 8 + (ln & 3) * 2;
            float li0 = 1.0f / l_s[jc], li1 = 1.0f / l_s[jc + 1];
            const float* cc = bacc[mt * 4 + nf];
            float vv[4] = {cc[0] * li0, cc[1] * li1, cc[2] * li0, cc[3] * li1};
            int ee[4] = {r0, r0, r0 + 8, r0 + 8};
            int jj[4] = {jc, jc + 1, jc, jc + 1};
#pragma unroll
            for (int q = 0; q < 4; ++q) {
                __nv_bfloat16 hv = __float2bfloat16(vv[q]);
                __nv_bfloat16 lv = __float2bfloat16(vv[q] - __bfloat162float(hv));
                size_t base = (size_t)(qb + jj[q]) * HE + h * E + ee[q];
                g_bh[base] = hv;
                g_bl[base] = lv;
            }
        }
    }
}

// ---------------------------------------------------------------------------
#define O_AH 0
#define O_AL 18432
#define O_BH 36864
#define O_BL 41472

__global__ __launch_bounds__(256) void gemm_out_tc(float* __restrict__ out) {
    __shared__ __align__(16) char sm2[46080];
    const uint32_t sb = smem_u32(sm2);
    const int t = threadIdx.x, w = t >> 5, ln = t & 31;
    const int bn = blockIdx.x * 32;
    const int mbase = w * 16;
    const int mA = ln >> 3, g8 = ln & 7;
    const int aRow = mbase + g8 + (mA & 1) * 8;
    const int aCol = (mA >> 1) * 8;
    const int bRow = g8 + (mA >> 1) * 8;
    const int bCol = (mA & 1) * 8;

    float acc[4][4];
#pragma unroll
    for (int u = 0; u < 4; u++)
#pragma unroll
        for (int v = 0; v < 4; v++) acc[u][v] = 0.f;

    for (int kc = 0; kc < 16; ++kc) {
        const int k0 = kc * 64;
        __syncthreads();
#pragma unroll
        for (int r = 0; r < 4; ++r) {
            int id = t + r * 256, row = id >> 3, c8 = id & 7;
            *(uint4*)(sm2 + O_AH + row * 144 + c8 * 16) =
                *((const uint4*)(g_Ah + (size_t)row * HE + k0) + c8);
            *(uint4*)(sm2 + O_AL + row * 144 + c8 * 16) =
                *((const uint4*)(g_Al + (size_t)row * HE + k0) + c8);
        }
        {
            int row = t >> 3, c8 = t & 7;
            *(uint4*)(sm2 + O_BH + row * 144 + c8 * 16) =
                *((const uint4*)(g_bh + (size_t)(bn + row) * HE + k0) + c8);
            *(uint4*)(sm2 + O_BL + row * 144 + c8 * 16) =
                *((const uint4*)(g_bl + (size_t)(bn + row) * HE + k0) + c8);
        }
        __syncthreads();
#pragma unroll
        for (int kf = 0; kf < 4; ++kf) {
            int ko = kf * 16;
            uint32_t ah[4], al[4];
            uint32_t aoff = (uint32_t)((aRow * 72 + ko + aCol) * 2);
            ldsm4(ah, sb + O_AH + aoff);
            ldsm4(al, sb + O_AL + aoff);
#pragma unroll
            for (int np = 0; np < 2; ++np) {
                int n16 = np * 16;
                uint32_t bh[4], bl[4];
                uint32_t boff = (uint32_t)(((n16 + bRow) * 72 + ko + bCol) * 2);
                ldsm4(bh, sb + O_BH + boff);
                ldsm4(bl, sb + O_BL + boff);
                mma_bf16(acc[np * 2], ah, bh);
                mma_bf16(acc[np * 2], ah, bl);
                mma_bf16(acc[np * 2], al, bh);
                mma_bf16(acc[np * 2 + 1], ah, bh + 2);
                mma_bf16(acc[np * 2 + 1], ah, bl + 2);
                mma_bf16(acc[np * 2 + 1], al, bh + 2);
            }
        }
    }
    const int r0 = mbase + (ln >> 2);
#pragma unroll
    for (int nf = 0; nf < 4; ++nf) {
        int j0 = bn + nf * 8 + (ln & 3) * 2;
        int ee[4] = {r0, r0, r0 + 8, r0 + 8};
        int jj[4] = {j0, j0 + 1, j0, j0 + 1};
#pragma unroll
        for (int q = 0; q < 4; ++q) {
            int dst = (jj[q] < L - 1) ? (E + jj[q] * E + ee[q]) : (2 * E * L + ee[q]);
            out[dst] = acc[nf][q];
        }
    }
}

// ---------------------------------------------------------------------------
extern "C" void kernel_launch(void* const* d_in, const int* in_sizes, int n_in,
                              void* d_out, int out_size) {
    const int* sq = (const int*)d_in[0];
    const int* cq = (const int*)d_in[1];
    const float* ir = (const float*)d_in[2];
    const float* uir = (const float*)d_in[3];
    const float* wr = (const float*)d_in[4];
    const float* Wq = (const float*)d_in[5];
    const float* Wk = (const float*)d_in[6];
    const float* Wv = (const float*)d_in[7];
    const float* Hagg = (const float*)d_in[8];
    float* out = (float*)d_out;
    cudaFuncSetAttribute(attn_kernel, cudaFuncAttributeMaxDynamicSharedMemorySize, ATTN_SMEM);
    build_I_kernel<<<(E * L) / 256, 256>>>(sq, cq, ir, wr, uir, out);
    prep_A_kernel<<<256, 256>>>(Hagg);
    gemm_qkv_kernel<<<dim3(32, 16, 3), 256>>>(Wq, Wk, Wv);
    attn_kernel<<<512, 128, ATTN_SMEM>>>();
    gemm_out_tc<<<64, 256>>>(out);
}

// round 9
// speedup vs baseline: 1.0442x; 1.0442x over previous
#include <cuda_runtime.h>
#include <cuda_bf16.h>
#include <math.h>
#include <stdint.h>

#define E 128
#define H 8
#define L 2048
#define HE 1024
#define HEL (HE * L)
#define NITEMS 50000
#define WAMT 5
#define SCALE_F 0.08838834764831845f

__device__ float g_I[E * L];
__device__ __nv_bfloat16 g_Qh[H * L * E], g_Ql[H * L * E];   // [h][l][e], pre-scaled
__device__ __nv_bfloat16 g_Kh[H * L * E], g_Kl[H * L * E];   // [h][l][e]
__device__ __nv_bfloat16 g_Vh[H * E * L], g_Vl[H * E * L];   // [h][e][l]
__device__ __nv_bfloat16 g_bh[L * HE], g_bl[L * HE];         // [l][he]
__device__ __nv_bfloat16 g_Ah[E * HE], g_Al[E * HE];         // [e_out][k]

__device__ __forceinline__ uint32_t smem_u32(const void* p) {
    return (uint32_t)__cvta_generic_to_shared(p);
}
__device__ __forceinline__ void ldsm4(uint32_t* r, uint32_t a) {
    asm volatile("ldmatrix.sync.aligned.m8n8.x4.shared.b16 {%0,%1,%2,%3}, [%4];"
                 : "=r"(r[0]), "=r"(r[1]), "=r"(r[2]), "=r"(r[3]) : "r"(a));
}
__device__ __forceinline__ void ldsm4t(uint32_t* r, uint32_t a) {
    asm volatile("ldmatrix.sync.aligned.m8n8.x4.trans.shared.b16 {%0,%1,%2,%3}, [%4];"
                 : "=r"(r[0]), "=r"(r[1]), "=r"(r[2]), "=r"(r[3]) : "r"(a));
}
__device__ __forceinline__ void mma_bf16(float* c, const uint32_t* a, const uint32_t* b) {
    asm volatile("mma.sync.aligned.m16n8k16.row.col.f32.bf16.bf16.f32 "
                 "{%0,%1,%2,%3}, {%4,%5,%6,%7}, {%8,%9}, {%0,%1,%2,%3};"
                 : "+f"(c[0]), "+f"(c[1]), "+f"(c[2]), "+f"(c[3])
                 : "r"(a[0]), "r"(a[1]), "r"(a[2]), "r"(a[3]), "r"(b[0]), "r"(b[1]));
}
__device__ __forceinline__ void split2(float a, float b, __nv_bfloat162& h, __nv_bfloat162& l) {
    h = __floats2bfloat162_rn(a, b);
    float2 r = __bfloat1622float2(h);
    l = __floats2bfloat162_rn(a - r.x, b - r.y);
}
#define CPA16(dst, src) \
    asm volatile("cp.async.cg.shared.global [%0], [%1], 16;" :: "r"(dst), "l"(src) : "memory")
#define CPA_COMMIT() asm volatile("cp.async.commit_group;" ::: "memory")
#define CPA_WAIT(n)  asm volatile("cp.async.wait_group %0;" :: "n"(n) : "memory")

// ---------------------------------------------------------------------------
__global__ void build_I_kernel(const int* __restrict__ sq, const int* __restrict__ cq,
                               const float* __restrict__ ir, const float* __restrict__ wr,
                               const float* __restrict__ uir, float* __restrict__ out) {
    int idx = blockIdx.x * blockDim.x + threadIdx.x;
    if (idx < E) out[idx] = uir[idx];
    if (idx >= E * L) return;
    int e = idx & 127, l = idx >> 7;
    float iq = ir[e * NITEMS + sq[l]];
    g_I[e * L + l] = iq + wr[e * WAMT + cq[l]];
    out[E * L + idx] = iq;
}

__global__ void prep_A_kernel(const float* __restrict__ A) {
    int idx = blockIdx.x * blockDim.x + threadIdx.x;
    int i2 = idx * 2;
    float2 f = *(const float2*)&A[i2];
    __nv_bfloat162 hh, ll;
    split2(f.x, f.y, hh, ll);
    *(__nv_bfloat162*)&g_Ah[i2] = hh;
    *(__nv_bfloat162*)&g_Al[i2] = ll;
}

// ---------------------------------------------------------------------------
__global__ __launch_bounds__(256) void gemm_qkv_kernel(const float* __restrict__ Wq,
                                                       const float* __restrict__ Wk,
                                                       const float* __restrict__ Wv) {
    __shared__ float As[64 * 68], Bs[64 * 68];
    const float* W = (blockIdx.z == 0) ? Wq : (blockIdx.z == 1 ? Wk : Wv);
    const int bm = blockIdx.y * 64, bn = blockIdx.x * 64;
    const int t = threadIdx.x, tx = t & 15, ty = t >> 4;
    float acc[4][4];
#pragma unroll
    for (int u = 0; u < 4; u++)
#pragma unroll
        for (int v = 0; v < 4; v++) acc[u][v] = 0.f;
    for (int k0 = 0; k0 < 128; k0 += 64) {
#pragma unroll
        for (int r = 0; r < 4; ++r) {
            int id = t + r * 256, m = id >> 4, kq = id & 15;
            float4 w4 = *(const float4*)&W[(bm + m) * 128 + k0 + kq * 4];
            As[(kq * 4 + 0) * 68 + m] = w4.x; As[(kq * 4 + 1) * 68 + m] = w4.y;
            As[(kq * 4 + 2) * 68 + m] = w4.z; As[(kq * 4 + 3) * 68 + m] = w4.w;
        }
#pragma unroll
        for (int r = 0; r < 4; ++r) {
            int id = t + r * 256, k = id >> 4, n4 = (id & 15) << 2;
            *(float4*)&Bs[k * 68 + n4] = *(const float4*)&g_I[(size_t)(k0 + k) * L + bn + n4];
        }
        __syncthreads();
#pragma unroll 8
        for (int k = 0; k < 64; ++k) {
            float4 a4 = *(const float4*)&As[k * 68 + ty * 4];
            float4 b4 = *(const float4*)&Bs[k * 68 + tx * 4];
            float a[4] = {a4.x, a4.y, a4.z, a4.w}, b[4] = {b4.x, b4.y, b4.z, b4.w};
#pragma unroll
            for (int u = 0; u < 4; u++)
#pragma unroll
                for (int v = 0; v < 4; v++) acc[u][v] = fmaf(a[u], b[v], acc[u][v]);
        }
        __syncthreads();
    }
    const int m0 = bm + ty * 4;
    const int n0 = bn + tx * 4;
    const int h = m0 >> 7, e0 = m0 & 127;
    if (blockIdx.z < 2) {
        __nv_bfloat16* Dh = blockIdx.z ? g_Kh : g_Qh;
        __nv_bfloat16* Dl = blockIdx.z ? g_Kl : g_Ql;
        const float s = blockIdx.z ? 1.0f : SCALE_F;
#pragma unroll
        for (int v = 0; v < 4; ++v) {
            __nv_bfloat162 h01, l01, h23, l23;
            split2(acc[0][v] * s, acc[1][v] * s, h01, l01);
            split2(acc[2][v] * s, acc[3][v] * s, h23, l23);
            size_t base = ((size_t)h * L + n0 + v) * E + e0;
            *(__nv_bfloat162*)&Dh[base] = h01;
            *(__nv_bfloat162*)&Dh[base + 2] = h23;
            *(__nv_bfloat162*)&Dl[base] = l01;
            *(__nv_bfloat162*)&Dl[base + 2] = l23;
        }
    } else {
#pragma unroll
        for (int u = 0; u < 4; ++u) {
            __nv_bfloat162 h01, l01, h23, l23;
            split2(acc[u][0], acc[u][1], h01, l01);
            split2(acc[u][2], acc[u][3], h23, l23);
            size_t base = ((size_t)h * E + e0 + u) * L + n0;
            *(__nv_bfloat162*)&g_Vh[base] = h01;
            *(__nv_bfloat162*)&g_Vh[base + 2] = h23;
            *(__nv_bfloat162*)&g_Vl[base] = l01;
            *(__nv_bfloat162*)&g_Vl[base + 2] = l23;
        }
    }
}

// ---------------------------------------------------------------------------
// Flash attention, 256 thr, 64-q tiles, double-buffered K/V via cp.async.
// Q [j][e] stride 136, K [i][e] stride 136, V [e][i] stride 72, P [i][j] stride 72.
// ---------------------------------------------------------------------------
#define SQK 136
#define SVP 72
#define S_QH 0
#define S_QL 17408
#define S_KV 34816
#define KSZ  17408
#define VSZ  18432
#define BUFSZ (2 * KSZ + 2 * VSZ)      /* 71680 */
#define S_PH (S_KV + 2 * BUFSZ)        /* 178176 */
#define S_PL (S_PH + 9216)             /* 187392 */
#define S_LS 196608
#define S_RED 196864
#define ATTN_SMEM 197888

__device__ __forceinline__ void prefetch_kv(uint32_t sb, int buf,
                                            const __nv_bfloat16* Kh, const __nv_bfloat16* Kl,
                                            const __nv_bfloat16* Vh, const __nv_bfloat16* Vl,
                                            int ib, int t) {
    const uint32_t kb = sb + S_KV + buf * BUFSZ;
    // K: 64 rows x 16 chunks of 16B, hi + lo
#pragma unroll
    for (int r = 0; r < 4; ++r) {
        int id = t + r * 256, row = id >> 4, c16 = id & 15;
        const char* sh = (const char*)(Kh + (size_t)(ib * 64 + row) * E) + c16 * 16;
        const char* sl = (const char*)(Kl + (size_t)(ib * 64 + row) * E) + c16 * 16;
        CPA16(kb + row * 272 + c16 * 16, sh);
        CPA16(kb + KSZ + row * 272 + c16 * 16, sl);
    }
    // V: 128 rows x 8 chunks, hi + lo
    const uint32_t vb = kb + 2 * KSZ;
#pragma unroll
    for (int r = 0; r < 4; ++r) {
        int id = t + r * 256, row = id >> 3, c8 = id & 7;
        const char* sh = (const char*)(Vh + (size_t)row * L + ib * 64) + c8 * 16;
        const char* sl = (const char*)(Vl + (size_t)row * L + ib * 64) + c8 * 16;
        CPA16(vb + row * 144 + c8 * 16, sh);
        CPA16(vb + VSZ + row * 144 + c8 * 16, sl);
    }
    CPA_COMMIT();
}

__global__ __launch_bounds__(256, 1) void attn_kernel() {
    extern __shared__ __align__(128) char smc[];
    const uint32_t sb = smem_u32(smc);
    const int t = threadIdx.x, w = t >> 5, ln = t & 31;
    const int h = blockIdx.y, px = blockIdx.x;
    float* l_s = (float*)(smc + S_LS);
    float* red = (float*)(smc + S_RED);

    const __nv_bfloat16* Qh = g_Qh + (size_t)h * L * E;
    const __nv_bfloat16* Ql = g_Ql + (size_t)h * L * E;
    const __nv_bfloat16* Kh = g_Kh + (size_t)h * L * E;
    const __nv_bfloat16* Kl = g_Kl + (size_t)h * L * E;
    const __nv_bfloat16* Vh = g_Vh + (size_t)h * E * L;
    const __nv_bfloat16* Vl = g_Vl + (size_t)h * E * L;

    const int wi = w & 3, wj = w >> 2;
    const int iw = wi * 16, jw = wj * 32;
    const int mA = ln >> 3, g8 = ln & 7;
    const int sArow = iw + g8 + (mA & 1) * 8;
    const int sAcol = (mA >> 1) * 8;
    const int sBrow = g8 + (mA >> 1) * 8;
    const int sBcol = (mA & 1) * 8;
    const int ew = w * 16;
    const int pArow = ew + g8 + (mA & 1) * 8;
    const int pAcol = (mA >> 1) * 8;
    const int pBrow = g8 + (mA & 1) * 8;
    const int pBcol = (mA >> 1) * 8;

#pragma unroll 1
    for (int ts = 0; ts < 2; ++ts) {
        const int jt = ts ? px : (31 - px);
        const int qb = jt << 6;
        __syncthreads();   // previous tile fully done (buffers + l_s free)

        prefetch_kv(sb, 0, Kh, Kl, Vh, Vl, 0, t);

        // Q tile copy (regular loads)
#pragma unroll
        for (int r = 0; r < 4; ++r) {
            int id = t + r * 256, row = id >> 4, c16 = id & 15;
            *(uint4*)(smc + S_QH + row * 272 + c16 * 16) =
                *((const uint4*)(Qh + (size_t)(qb + row) * E) + c16);
            *(uint4*)(smc + S_QL + row * 272 + c16 * 16) =
                *((const uint4*)(Ql + (size_t)(qb + row) * E) + c16);
        }
        if (t < 64) l_s[t] = 0.f;

        float bacc[8][4];
#pragma unroll
        for (int u = 0; u < 8; u++)
#pragma unroll
            for (int v = 0; v < 4; v++) bacc[u][v] = 0.f;

#pragma unroll 1
        for (int ib = 0; ib <= jt; ++ib) {
            __syncthreads();   // all PV(ib-1) done -> buf[(ib+1)&1] free; Q/l_s visible
            if (ib < jt) {
                prefetch_kv(sb, (ib + 1) & 1, Kh, Kl, Vh, Vl, ib + 1, t);
                CPA_WAIT(1);
            } else {
                CPA_WAIT(0);
            }
            __syncthreads();   // buf[ib&1] data visible to all warps

            const uint32_t kH = sb + S_KV + (ib & 1) * BUFSZ;
            const uint32_t kL = kH + KSZ;
            const uint32_t vH = kH + 2 * KSZ;
            const uint32_t vL = vH + VSZ;

            // ---- S = K^T Q, 3-term ----
            float sacc[4][4];
#pragma unroll
            for (int u = 0; u < 4; u++)
#pragma unroll
                for (int v = 0; v < 4; v++) sacc[u][v] = 0.f;
#pragma unroll
            for (int ks = 0; ks < 8; ++ks) {
                int e0 = ks * 16;
                uint32_t ah[4], al[4];
                ldsm4(ah, kH + (uint32_t)((sArow * SQK + e0 + sAcol) * 2));
                ldsm4(al, kL + (uint32_t)((sArow * SQK + e0 + sAcol) * 2));
#pragma unroll
                for (int np = 0; np < 2; ++np) {
                    int j16 = jw + np * 16;
                    uint32_t bh[4], bl[4];
                    uint32_t boff = (uint32_t)(((j16 + sBrow) * SQK + e0 + sBcol) * 2);
                    ldsm4(bh, sb + S_QH + boff);
                    ldsm4(bl, sb + S_QL + boff);
                    mma_bf16(sacc[np * 2], ah, bh);
                    mma_bf16(sacc[np * 2], ah, bl);
                    mma_bf16(sacc[np * 2], al, bh);
                    mma_bf16(sacc[np * 2 + 1], ah, bh + 2);
                    mma_bf16(sacc[np * 2 + 1], ah, bl + 2);
                    mma_bf16(sacc[np * 2 + 1], al, bh + 2);
                }
            }

            // ---- exp + causal mask + P hi/lo + column sums ----
            const int rl0 = iw + (ln >> 2);
            const int i0g = ib * 64 + rl0;
#pragma unroll
            for (int nt = 0; nt < 4; ++nt) {
                int jc = jw + nt * 8 + (ln & 3) * 2;
                int jg = qb + jc;
                float p0 = (i0g <= jg)     ? __expf(sacc[nt][0]) : 0.f;
                float p1 = (i0g <= jg + 1) ? __expf(sacc[nt][1]) : 0.f;
                float p2 = (i0g + 8 <= jg)     ? __expf(sacc[nt][2]) : 0.f;
                float p3 = (i0g + 8 <= jg + 1) ? __expf(sacc[nt][3]) : 0.f;
                __nv_bfloat162 h01, l01, h23, l23;
                split2(p0, p1, h01, l01);
                split2(p2, p3, h23, l23);
                int o0 = (rl0 * SVP + jc) * 2;
                int o1 = ((rl0 + 8) * SVP + jc) * 2;
                *(__nv_bfloat162*)(smc + S_PH + o0) = h01;
                *(__nv_bfloat162*)(smc + S_PH + o1) = h23;
                *(__nv_bfloat162*)(smc + S_PL + o0) = l01;
                *(__nv_bfloat162*)(smc + S_PL + o1) = l23;
                float cs0 = p0 + p2, cs1 = p1 + p3;
#pragma unroll
                for (int off = 4; off < 32; off <<= 1) {
                    cs0 += __shfl_xor_sync(0xffffffffu, cs0, off);
                    cs1 += __shfl_xor_sync(0xffffffffu, cs1, off);
                }
                if (ln < 4) { red[wi * 64 + jc] = cs0; red[wi * 64 + jc + 1] = cs1; }
            }
            __syncthreads();   // P + red ready
            if (t < 64) l_s[t] += red[t] + red[64 + t] + red[128 + t] + red[192 + t];

            // ---- PV, 3-term ----
#pragma unroll
            for (int ks = 0; ks < 4; ++ks) {
                int i0 = ks * 16;
                uint32_t ah[4], al[4];
                uint32_t aoff = (uint32_t)((pArow * SVP + i0 + pAcol) * 2);
                ldsm4(ah, vH + aoff);
                ldsm4(al, vL + aoff);
#pragma unroll
                for (int np = 0; np < 4; ++np) {
                    int j16 = np * 16;
                    uint32_t bh[4], bl[4];
                    uint32_t boff = (uint32_t)(((i0 + pBrow) * SVP + j16 + pBcol) * 2);
                    ldsm4t(bh, sb + S_PH + boff);
                    ldsm4t(bl, sb + S_PL + boff);
                    mma_bf16(bacc[np * 2], ah, bh);
                    mma_bf16(bacc[np * 2], ah, bl);
                    mma_bf16(bacc[np * 2], al, bh);
                    mma_bf16(bacc[np * 2 + 1], ah, bh + 2);
                    mma_bf16(bacc[np * 2 + 1], ah, bl + 2);
                    mma_bf16(bacc[np * 2 + 1], al, bh + 2);
                }
            }
        }
        __syncthreads();   // l_s final

        // epilogue: normalize + split + store b hi/lo at [l][he]
        const int r0 = ew + (ln >> 2);
#pragma unroll
        for (int nt = 0; nt < 8; ++nt) {
            int jc = nt * 8 + (ln & 3) * 2;
            float li0 = 1.0f / l_s[jc], li1 = 1.0f / l_s[jc + 1];
            float vv[4] = {bacc[nt][0] * li0, bacc[nt][1] * li1,
                           bacc[nt][2] * li0, bacc[nt][3] * li1};
            int ee[4] = {r0, r0, r0 + 8, r0 + 8};
            int jj[4] = {jc, jc + 1, jc, jc + 1};
#pragma unroll
            for (int q = 0; q < 4; ++q) {
                __nv_bfloat16 hv = __float2bfloat16(vv[q]);
                __nv_bfloat16 lv = __float2bfloat16(vv[q] - __bfloat162float(hv));
                size_t base = (size_t)(qb + jj[q]) * HE + h * E + ee[q];
                g_bh[base] = hv;
                g_bl[base] = lv;
            }
        }
    }
}

// ---------------------------------------------------------------------------
#define O_AH 0
#define O_AL 18432
#define O_BH 36864
#define O_BL 41472

__global__ __launch_bounds__(256) void gemm_out_tc(float* __restrict__ out) {
    __shared__ __align__(16) char sm2[46080];
    const uint32_t sb = smem_u32(sm2);
    const int t = threadIdx.x, w = t >> 5, ln = t & 31;
    const int bn = blockIdx.x * 32;
    const int mbase = w * 16;
    const int mA = ln >> 3, g8 = ln & 7;
    const int aRow = mbase + g8 + (mA & 1) * 8;
    const int aCol = (mA >> 1) * 8;
    const int bRow = g8 + (mA >> 1) * 8;
    const int bCol = (mA & 1) * 8;

    float acc[4][4];
#pragma unroll
    for (int u = 0; u < 4; u++)
#pragma unroll
        for (int v = 0; v < 4; v++) acc[u][v] = 0.f;

    for (int kc = 0; kc < 16; ++kc) {
        const int k0 = kc * 64;
        __syncthreads();
#pragma unroll
        for (int r = 0; r < 4; ++r) {
            int id = t + r * 256, row = id >> 3, c8 = id & 7;
            *(uint4*)(sm2 + O_AH + row * 144 + c8 * 16) =
                *((const uint4*)(g_Ah + (size_t)row * HE + k0) + c8);
            *(uint4*)(sm2 + O_AL + row * 144 + c8 * 16) =
                *((const uint4*)(g_Al + (size_t)row * HE + k0) + c8);
        }
        {
            int row = t >> 3, c8 = t & 7;
            *(uint4*)(sm2 + O_BH + row * 144 + c8 * 16) =
                *((const uint4*)(g_bh + (size_t)(bn + row) * HE + k0) + c8);
            *(uint4*)(sm2 + O_BL + row * 144 + c8 * 16) =
                *((const uint4*)(g_bl + (size_t)(bn + row) * HE + k0) + c8);
        }
        __syncthreads();
#pragma unroll
        for (int kf = 0; kf < 4; ++kf) {
            int ko = kf * 16;
            uint32_t ah[4], al[4];
            uint32_t aoff = (uint32_t)((aRow * 72 + ko + aCol) * 2);
            ldsm4(ah, sb + O_AH + aoff);
            ldsm4(al, sb + O_AL + aoff);
#pragma unroll
            for (int np = 0; np < 2; ++np) {
                int n16 = np * 16;
                uint32_t bh[4], bl[4];
                uint32_t boff = (uint32_t)(((n16 + bRow) * 72 + ko + bCol) * 2);
                ldsm4(bh, sb + O_BH + boff);
                ldsm4(bl, sb + O_BL + boff);
                mma_bf16(acc[np * 2], ah, bh);
                mma_bf16(acc[np * 2], ah, bl);
                mma_bf16(acc[np * 2], al, bh);
                mma_bf16(acc[np * 2 + 1], ah, bh + 2);
                mma_bf16(acc[np * 2 + 1], ah, bl + 2);
                mma_bf16(acc[np * 2 + 1], al, bh + 2);
            }
        }
    }
    const int r0 = mbase + (ln >> 2);
#pragma unroll
    for (int nf = 0; nf < 4; ++nf) {
        int j0 = bn + nf * 8 + (ln & 3) * 2;
        int ee[4] = {r0, r0, r0 + 8, r0 + 8};
        int jj[4] = {j0, j0 + 1, j0, j0 + 1};
#pragma unroll
        for (int q = 0; q < 4; ++q) {
            int dst = (jj[q] < L - 1) ? (E + jj[q] * E + ee[q]) : (2 * E * L + ee[q]);
            out[dst] = acc[nf][q];
        }
    }
}

// ---------------------------------------------------------------------------
extern "C" void kernel_launch(void* const* d_in, const int* in_sizes, int n_in,
                              void* d_out, int out_size) {
    const int* sq = (const int*)d_in[0];
    const int* cq = (const int*)d_in[1];
    const float* ir = (const float*)d_in[2];
    const float* uir = (const float*)d_in[3];
    const float* wr = (const float*)d_in[4];
    const float* Wq = (const float*)d_in[5];
    const float* Wk = (const float*)d_in[6];
    const float* Wv = (const float*)d_in[7];
    const float* Hagg = (const float*)d_in[8];
    float* out = (float*)d_out;
    cudaFuncSetAttribute(attn_kernel, cudaFuncAttributeMaxDynamicSharedMemorySize, ATTN_SMEM);
    build_I_kernel<<<(E * L) / 256, 256>>>(sq, cq, ir, wr, uir, out);
    prep_A_kernel<<<256, 256>>>(Hagg);
    gemm_qkv_kernel<<<dim3(32, 16, 3), 256>>>(Wq, Wk, Wv);
    attn_kernel<<<dim3(16, H), 256, ATTN_SMEM>>>();
    gemm_out_tc<<<64, 256>>>(out);
}

// round 10
// speedup vs baseline: 1.1587x; 1.1097x over previous
#include <cuda_runtime.h>
#include <cuda_bf16.h>
#include <math.h>
#include <stdint.h>

#define E 128
#define H 8
#define L 2048
#define HE 1024
#define HEL (HE * L)
#define NITEMS 50000
#define WAMT 5
#define SCALE_F 0.08838834764831845f

__device__ float g_I[E * L];
__device__ __nv_bfloat16 g_Qh[H * L * E], g_Ql[H * L * E];   // [h][l][e], pre-scaled
__device__ __nv_bfloat16 g_Kh[H * L * E], g_Kl[H * L * E];   // [h][l][e]
__device__ __nv_bfloat16 g_Vh[H * E * L], g_Vl[H * E * L];   // [h][e][l]
__device__ __nv_bfloat16 g_bh[L * HE], g_bl[L * HE];         // [l][he]
__device__ __nv_bfloat16 g_Ah[E * HE], g_Al[E * HE];         // [e_out][k]

__device__ __forceinline__ uint32_t smem_u32(const void* p) {
    return (uint32_t)__cvta_generic_to_shared(p);
}
__device__ __forceinline__ void ldsm4(uint32_t* r, uint32_t a) {
    asm volatile("ldmatrix.sync.aligned.m8n8.x4.shared.b16 {%0,%1,%2,%3}, [%4];"
                 : "=r"(r[0]), "=r"(r[1]), "=r"(r[2]), "=r"(r[3]) : "r"(a));
}
__device__ __forceinline__ void mma_bf16(float* c, const uint32_t* a, const uint32_t* b) {
    asm volatile("mma.sync.aligned.m16n8k16.row.col.f32.bf16.bf16.f32 "
                 "{%0,%1,%2,%3}, {%4,%5,%6,%7}, {%8,%9}, {%0,%1,%2,%3};"
                 : "+f"(c[0]), "+f"(c[1]), "+f"(c[2]), "+f"(c[3])
                 : "r"(a[0]), "r"(a[1]), "r"(a[2]), "r"(a[3]), "r"(b[0]), "r"(b[1]));
}
__device__ __forceinline__ void split2(float a, float b, __nv_bfloat162& h, __nv_bfloat162& l) {
    h = __floats2bfloat162_rn(a, b);
    float2 r = __bfloat1622float2(h);
    l = __floats2bfloat162_rn(a - r.x, b - r.y);
}
#define CPA16(dst, src) \
    asm volatile("cp.async.cg.shared.global [%0], [%1], 16;" :: "r"(dst), "l"(src) : "memory")
#define CPA_COMMIT() asm volatile("cp.async.commit_group;" ::: "memory")
#define CPA_WAIT(n)  asm volatile("cp.async.wait_group %0;" :: "n"(n) : "memory")

// ---------------------------------------------------------------------------
__global__ void build_I_kernel(const int* __restrict__ sq, const int* __restrict__ cq,
                               const float* __restrict__ ir, const float* __restrict__ wr,
                               const float* __restrict__ uir, float* __restrict__ out) {
    int idx = blockIdx.x * blockDim.x + threadIdx.x;
    if (idx < E) out[idx] = uir[idx];
    if (idx >= E * L) return;
    int e = idx & 127, l = idx >> 7;
    float iq = ir[e * NITEMS + sq[l]];
    g_I[e * L + l] = iq + wr[e * WAMT + cq[l]];
    out[E * L + idx] = iq;
}

__global__ void prep_A_kernel(const float* __restrict__ A) {
    int idx = blockIdx.x * blockDim.x + threadIdx.x;
    int i2 = idx * 2;
    float2 f = *(const float2*)&A[i2];
    __nv_bfloat162 hh, ll;
    split2(f.x, f.y, hh, ll);
    *(__nv_bfloat162*)&g_Ah[i2] = hh;
    *(__nv_bfloat162*)&g_Al[i2] = ll;
}

// ---------------------------------------------------------------------------
__global__ __launch_bounds__(256) void gemm_qkv_kernel(const float* __restrict__ Wq,
                                                       const float* __restrict__ Wk,
                                                       const float* __restrict__ Wv) {
    __shared__ float As[64 * 68], Bs[64 * 68];
    const float* W = (blockIdx.z == 0) ? Wq : (blockIdx.z == 1 ? Wk : Wv);
    const int bm = blockIdx.y * 64, bn = blockIdx.x * 64;
    const int t = threadIdx.x, tx = t & 15, ty = t >> 4;
    float acc[4][4];
#pragma unroll
    for (int u = 0; u < 4; u++)
#pragma unroll
        for (int v = 0; v < 4; v++) acc[u][v] = 0.f;
    for (int k0 = 0; k0 < 128; k0 += 64) {
#pragma unroll
        for (int r = 0; r < 4; ++r) {
            int id = t + r * 256, m = id >> 4, kq = id & 15;
            float4 w4 = *(const float4*)&W[(bm + m) * 128 + k0 + kq * 4];
            As[(kq * 4 + 0) * 68 + m] = w4.x; As[(kq * 4 + 1) * 68 + m] = w4.y;
            As[(kq * 4 + 2) * 68 + m] = w4.z; As[(kq * 4 + 3) * 68 + m] = w4.w;
        }
#pragma unroll
        for (int r = 0; r < 4; ++r) {
            int id = t + r * 256, k = id >> 4, n4 = (id & 15) << 2;
            *(float4*)&Bs[k * 68 + n4] = *(const float4*)&g_I[(size_t)(k0 + k) * L + bn + n4];
        }
        __syncthreads();
#pragma unroll 8
        for (int k = 0; k < 64; ++k) {
            float4 a4 = *(const float4*)&As[k * 68 + ty * 4];
            float4 b4 = *(const float4*)&Bs[k * 68 + tx * 4];
            float a[4] = {a4.x, a4.y, a4.z, a4.w}, b[4] = {b4.x, b4.y, b4.z, b4.w};
#pragma unroll
            for (int u = 0; u < 4; u++)
#pragma unroll
                for (int v = 0; v < 4; v++) acc[u][v] = fmaf(a[u], b[v], acc[u][v]);
        }
        __syncthreads();
    }
    const int m0 = bm + ty * 4;
    const int n0 = bn + tx * 4;
    const int h = m0 >> 7, e0 = m0 & 127;
    if (blockIdx.z < 2) {
        __nv_bfloat16* Dh = blockIdx.z ? g_Kh : g_Qh;
        __nv_bfloat16* Dl = blockIdx.z ? g_Kl : g_Ql;
        const float s = blockIdx.z ? 1.0f : SCALE_F;
#pragma unroll
        for (int v = 0; v < 4; ++v) {
            __nv_bfloat162 h01, l01, h23, l23;
            split2(acc[0][v] * s, acc[1][v] * s, h01, l01);
            split2(acc[2][v] * s, acc[3][v] * s, h23, l23);
            size_t base = ((size_t)h * L + n0 + v) * E + e0;
            *(__nv_bfloat162*)&Dh[base] = h01;
            *(__nv_bfloat162*)&Dh[base + 2] = h23;
            *(__nv_bfloat162*)&Dl[base] = l01;
            *(__nv_bfloat162*)&Dl[base + 2] = l23;
        }
    } else {
#pragma unroll
        for (int u = 0; u < 4; ++u) {
            __nv_bfloat162 h01, l01, h23, l23;
            split2(acc[u][0], acc[u][1], h01, l01);
            split2(acc[u][2], acc[u][3], h23, l23);
            size_t base = ((size_t)h * E + e0 + u) * L + n0;
            *(__nv_bfloat162*)&g_Vh[base] = h01;
            *(__nv_bfloat162*)&g_Vh[base + 2] = h23;
            *(__nv_bfloat162*)&g_Vl[base] = l01;
            *(__nv_bfloat162*)&g_Vl[base + 2] = l23;
        }
    }
}

// ---------------------------------------------------------------------------
// Flash attention, register-resident P. 256 thr, 64-q tiles.
// Warp w: j16 = (w>>1)*16, i-half = (w&1)*32. S: M=j16 N=i32 K=e128.
// PV: M=j16 N=e128 K=i32, A=P from S fragments (registers).
// Warp pairs (2k,2k+1) combine partial b via smem exchange at tile end.
// ---------------------------------------------------------------------------
#define SQK 136
#define SV 72
#define S_QH 0
#define S_QL 17408
#define S_KV 34816
#define KSZ  17408
#define VSZ  18432
#define BUFSZ (2 * KSZ + 2 * VSZ)      /* 71680 */
#define S_XB (S_KV + BUFSZ)            /* exchange aliases buffer 1 */
#define ATTN_SMEM (S_KV + 2 * BUFSZ)   /* 178176 */

__device__ __forceinline__ void prefetch_kv(uint32_t sb, int buf,
                                            const __nv_bfloat16* Kh, const __nv_bfloat16* Kl,
                                            const __nv_bfloat16* Vh, const __nv_bfloat16* Vl,
                                            int ib, int t) {
    const uint32_t kb = sb + S_KV + buf * BUFSZ;
#pragma unroll
    for (int r = 0; r < 4; ++r) {
        int id = t + r * 256, row = id >> 4, c16 = id & 15;
        const char* sh = (const char*)(Kh + (size_t)(ib * 64 + row) * E) + c16 * 16;
        const char* sl = (const char*)(Kl + (size_t)(ib * 64 + row) * E) + c16 * 16;
        CPA16(kb + row * 272 + c16 * 16, sh);
        CPA16(kb + KSZ + row * 272 + c16 * 16, sl);
    }
    const uint32_t vb = kb + 2 * KSZ;
#pragma unroll
    for (int r = 0; r < 4; ++r) {
        int id = t + r * 256, row = id >> 3, c8 = id & 7;
        const char* sh = (const char*)(Vh + (size_t)row * L + ib * 64) + c8 * 16;
        const char* sl = (const char*)(Vl + (size_t)row * L + ib * 64) + c8 * 16;
        CPA16(vb + row * 144 + c8 * 16, sh);
        CPA16(vb + VSZ + row * 144 + c8 * 16, sl);
    }
    CPA_COMMIT();
}

__global__ __launch_bounds__(256, 1) void attn_kernel() {
    extern __shared__ __align__(128) char smc[];
    const uint32_t sb = smem_u32(smc);
    const int t = threadIdx.x, w = t >> 5, ln = t & 31;
    const int h = blockIdx.y, px = blockIdx.x;

    const __nv_bfloat16* Qh = g_Qh + (size_t)h * L * E;
    const __nv_bfloat16* Ql = g_Ql + (size_t)h * L * E;
    const __nv_bfloat16* Kh = g_Kh + (size_t)h * L * E;
    const __nv_bfloat16* Kl = g_Kl + (size_t)h * L * E;
    const __nv_bfloat16* Vh = g_Vh + (size_t)h * E * L;
    const __nv_bfloat16* Vl = g_Vl + (size_t)h * E * L;

    const int jw  = (w >> 1) * 16;      // warp's 16 query rows within tile
    const int ihw = (w & 1) * 32;       // warp's 32-key half of the step
    const int g   = ln >> 2;            // C/A row group
    const int q2  = (ln & 3) * 2;       // C/A col pair
    const int mA = ln >> 3, g8 = ln & 7;
    const int aRow = jw + g8 + (mA & 1) * 8;      // A (Q) ldsm row
    const int aCol = (mA >> 1) * 8;               // + e0
    const int bRow = g8 + (mA >> 1) * 8;          // B ldsm row offset
    const int bCol = (mA & 1) * 8;                // B ldsm col offset

#pragma unroll 1
    for (int ts = 0; ts < 2; ++ts) {
        const int jt = ts ? px : (31 - px);
        const int qb = jt << 6;
        __syncthreads();   // prior tile fully done (Q, buffers, XB free)

        prefetch_kv(sb, 0, Kh, Kl, Vh, Vl, 0, t);

        // Q tile copy
#pragma unroll
        for (int r = 0; r < 4; ++r) {
            int id = t + r * 256, row = id >> 4, c16 = id & 15;
            *(uint4*)(smc + S_QH + row * 272 + c16 * 16) =
                *((const uint4*)(Qh + (size_t)(qb + row) * E) + c16);
            *(uint4*)(smc + S_QL + row * 272 + c16 * 16) =
                *((const uint4*)(Ql + (size_t)(qb + row) * E) + c16);
        }

        float bacc[16][4];
#pragma unroll
        for (int u = 0; u < 16; u++)
#pragma unroll
            for (int v = 0; v < 4; v++) bacc[u][v] = 0.f;
        float lsum0 = 0.f, lsum1 = 0.f;
        const int jg0 = qb + jw + g, jg1 = jg0 + 8;

#pragma unroll 1
        for (int ib = 0; ib <= jt; ++ib) {
            __syncthreads();   // all reads of buf[ib-1] done; Q visible (ib=0)
            if (ib < jt) {
                prefetch_kv(sb, (ib + 1) & 1, Kh, Kl, Vh, Vl, ib + 1, t);
                CPA_WAIT(1);
            } else {
                CPA_WAIT(0);
            }
            __syncthreads();   // buf[ib&1] visible

            const uint32_t kH = sb + S_KV + (ib & 1) * BUFSZ;
            const uint32_t kL = kH + KSZ;
            const uint32_t vH = kH + 2 * KSZ;
            const uint32_t vL = vH + VSZ;

            // ---- S[j16][i32] = Q x K^T, 3-term ----
            float sacc[4][4];
#pragma unroll
            for (int u = 0; u < 4; u++)
#pragma unroll
                for (int v = 0; v < 4; v++) sacc[u][v] = 0.f;
#pragma unroll
            for (int ks = 0; ks < 8; ++ks) {
                int e0 = ks * 16;
                uint32_t ah[4], al[4];
                ldsm4(ah, sb + S_QH + (uint32_t)((aRow * SQK + e0 + aCol) * 2));
                ldsm4(al, sb + S_QL + (uint32_t)((aRow * SQK + e0 + aCol) * 2));
#pragma unroll
                for (int it = 0; it < 2; ++it) {
                    uint32_t bh[4], bl[4];
                    uint32_t boff = (uint32_t)(((ihw + it * 16 + bRow) * SQK + e0 + bCol) * 2);
                    ldsm4(bh, kH + boff);
                    ldsm4(bl, kL + boff);
                    mma_bf16(sacc[it * 2], ah, bh);
                    mma_bf16(sacc[it * 2], ah, bl);
                    mma_bf16(sacc[it * 2], al, bh);
                    mma_bf16(sacc[it * 2 + 1], ah, bh + 2);
                    mma_bf16(sacc[it * 2 + 1], ah, bl + 2);
                    mma_bf16(sacc[it * 2 + 1], al, bh + 2);
                }
            }

            // ---- exp + mask + pack P into A fragments (registers only) ----
            uint32_t aPh[2][4], aPl[2][4];
#pragma unroll
            for (int nf = 0; nf < 4; ++nf) {
                int ig = ib * 64 + ihw + nf * 8 + q2;
                float p0 = (ig     <= jg0) ? __expf(sacc[nf][0]) : 0.f;
                float p1 = (ig + 1 <= jg0) ? __expf(sacc[nf][1]) : 0.f;
                float p2 = (ig     <= jg1) ? __expf(sacc[nf][2]) : 0.f;
                float p3 = (ig + 1 <= jg1) ? __expf(sacc[nf][3]) : 0.f;
                lsum0 += p0 + p1;
                lsum1 += p2 + p3;
                __nv_bfloat162 h01, l01, h23, l23;
                split2(p0, p1, h01, l01);
                split2(p2, p3, h23, l23);
                int kb = nf >> 1, sub = (nf & 1) * 2;
                aPh[kb][sub]     = *(uint32_t*)&h01;
                aPh[kb][sub + 1] = *(uint32_t*)&h23;
                aPl[kb][sub]     = *(uint32_t*)&l01;
                aPl[kb][sub + 1] = *(uint32_t*)&l23;
            }

            // ---- PV: b[j16][e128] += P x V (A in registers), 3-term ----
#pragma unroll
            for (int kb = 0; kb < 2; ++kb) {
#pragma unroll
                for (int ef = 0; ef < 8; ++ef) {
                    uint32_t bh[4], bl[4];
                    uint32_t boff = (uint32_t)(((ef * 16 + bRow) * SV +
                                                ihw + kb * 16 + bCol) * 2);
                    ldsm4(bh, vH + boff);
                    ldsm4(bl, vL + boff);
                    mma_bf16(bacc[ef * 2], aPh[kb], bh);
                    mma_bf16(bacc[ef * 2], aPh[kb], bl);
                    mma_bf16(bacc[ef * 2], aPl[kb], bh);
                    mma_bf16(bacc[ef * 2 + 1], aPh[kb], bh + 2);
                    mma_bf16(bacc[ef * 2 + 1], aPh[kb], bl + 2);
                    mma_bf16(bacc[ef * 2 + 1], aPl[kb], bh + 2);
                }
            }
        }

        // ---- tile end: combine warp pairs, normalize, store ----
        __syncthreads();   // all PV reads of buffers done (XB aliases buf1)
        float* XB = (float*)(smc + S_XB);
        const int xbase = ((w >> 1) * 32 + ln) * 68;
        if (w & 1) {
#pragma unroll
            for (int nf = 0; nf < 16; ++nf) {
                XB[xbase + nf * 4 + 0] = bacc[nf][0];
                XB[xbase + nf * 4 + 1] = bacc[nf][1];
                XB[xbase + nf * 4 + 2] = bacc[nf][2];
                XB[xbase + nf * 4 + 3] = bacc[nf][3];
            }
            XB[xbase + 64] = lsum0;
            XB[xbase + 65] = lsum1;
        }
        __syncthreads();
        if (!(w & 1)) {
#pragma unroll
            for (int nf = 0; nf < 16; ++nf) {
                bacc[nf][0] += XB[xbase + nf * 4 + 0];
                bacc[nf][1] += XB[xbase + nf * 4 + 1];
                bacc[nf][2] += XB[xbase + nf * 4 + 2];
                bacc[nf][3] += XB[xbase + nf * 4 + 3];
            }
            lsum0 += XB[xbase + 64];
            lsum1 += XB[xbase + 65];
            lsum0 += __shfl_xor_sync(0xffffffffu, lsum0, 1);
            lsum0 += __shfl_xor_sync(0xffffffffu, lsum0, 2);
            lsum1 += __shfl_xor_sync(0xffffffffu, lsum1, 1);
            lsum1 += __shfl_xor_sync(0xffffffffu, lsum1, 2);
            float li0 = 1.0f / lsum0, li1 = 1.0f / lsum1;
            const int j0 = qb + jw + g;
#pragma unroll
            for (int nf = 0; nf < 16; ++nf) {
                int e0 = h * E + nf * 8 + q2;
                __nv_bfloat162 h01, l01, h23, l23;
                split2(bacc[nf][0] * li0, bacc[nf][1] * li0, h01, l01);
                split2(bacc[nf][2] * li1, bacc[nf][3] * li1, h23, l23);
                size_t b0 = (size_t)j0 * HE + e0;
                size_t b1 = (size_t)(j0 + 8) * HE + e0;
                *(__nv_bfloat162*)&g_bh[b0] = h01;
                *(__nv_bfloat162*)&g_bl[b0] = l01;
                *(__nv_bfloat162*)&g_bh[b1] = h23;
                *(__nv_bfloat162*)&g_bl[b1] = l23;
            }
        }
    }
}

// ---------------------------------------------------------------------------
#define O_AH 0
#define O_AL 18432
#define O_BH 36864
#define O_BL 41472

__global__ __launch_bounds__(256) void gemm_out_tc(float* __restrict__ out) {
    __shared__ __align__(16) char sm2[46080];
    const uint32_t sb = smem_u32(sm2);
    const int t = threadIdx.x, w = t >> 5, ln = t & 31;
    const int bn = blockIdx.x * 32;
    const int mbase = w * 16;
    const int mA = ln >> 3, g8 = ln & 7;
    const int aRow = mbase + g8 + (mA & 1) * 8;
    const int aCol = (mA >> 1) * 8;
    const int bRow = g8 + (mA >> 1) * 8;
    const int bCol = (mA & 1) * 8;

    float acc[4][4];
#pragma unroll
    for (int u = 0; u < 4; u++)
#pragma unroll
        for (int v = 0; v < 4; v++) acc[u][v] = 0.f;

    for (int kc = 0; kc < 16; ++kc) {
        const int k0 = kc * 64;
        __syncthreads();
#pragma unroll
        for (int r = 0; r < 4; ++r) {
            int id = t + r * 256, row = id >> 3, c8 = id & 7;
            *(uint4*)(sm2 + O_AH + row * 144 + c8 * 16) =
                *((const uint4*)(g_Ah + (size_t)row * HE + k0) + c8);
            *(uint4*)(sm2 + O_AL + row * 144 + c8 * 16) =
                *((const uint4*)(g_Al + (size_t)row * HE + k0) + c8);
        }
        {
            int row = t >> 3, c8 = t & 7;
            *(uint4*)(sm2 + O_BH + row * 144 + c8 * 16) =
                *((const uint4*)(g_bh + (size_t)(bn + row) * HE + k0) + c8);
            *(uint4*)(sm2 + O_BL + row * 144 + c8 * 16) =
                *((const uint4*)(g_bl + (size_t)(bn + row) * HE + k0) + c8);
        }
        __syncthreads();
#pragma unroll
        for (int kf = 0; kf < 4; ++kf) {
            int ko = kf * 16;
            uint32_t ah[4], al[4];
            uint32_t aoff = (uint32_t)((aRow * 72 + ko + aCol) * 2);
            ldsm4(ah, sb + O_AH + aoff);
            ldsm4(al, sb + O_AL + aoff);
#pragma unroll
            for (int np = 0; np < 2; ++np) {
                int n16 = np * 16;
                uint32_t bh[4], bl[4];
                uint32_t boff = (uint32_t)(((n16 + bRow) * 72 + ko + bCol) * 2);
                ldsm4(bh, sb + O_BH + boff);
                ldsm4(bl, sb + O_BL + boff);
                mma_bf16(acc[np * 2], ah, bh);
                mma_bf16(acc[np * 2], ah, bl);
                mma_bf16(acc[np * 2], al, bh);
                mma_bf16(acc[np * 2 + 1], ah, bh + 2);
                mma_bf16(acc[np * 2 + 1], ah, bl + 2);
                mma_bf16(acc[np * 2 + 1], al, bh + 2);
            }
        }
    }
    const int r0 = mbase + (ln >> 2);
#pragma unroll
    for (int nf = 0; nf < 4; ++nf) {
        int j0 = bn + nf * 8 + (ln & 3) * 2;
        int ee[4] = {r0, r0, r0 + 8, r0 + 8};
        int jj[4] = {j0, j0 + 1, j0, j0 + 1};
#pragma unroll
        for (int q = 0; q < 4; ++q) {
            int dst = (jj[q] < L - 1) ? (E + jj[q] * E + ee[q]) : (2 * E * L + ee[q]);
            out[dst] = acc[nf][q];
        }
    }
}

// ---------------------------------------------------------------------------
extern "C" void kernel_launch(void* const* d_in, const int* in_sizes, int n_in,
                              void* d_out, int out_size) {
    const int* sq = (const int*)d_in[0];
    const int* cq = (const int*)d_in[1];
    const float* ir = (const float*)d_in[2];
    const float* uir = (const float*)d_in[3];
    const float* wr = (const float*)d_in[4];
    const float* Wq = (const float*)d_in[5];
    const float* Wk = (const float*)d_in[6];
    const float* Wv = (const float*)d_in[7];
    const float* Hagg = (const float*)d_in[8];
    float* out = (float*)d_out;
    cudaFuncSetAttribute(attn_kernel, cudaFuncAttributeMaxDynamicSharedMemorySize, ATTN_SMEM);
    build_I_kernel<<<(E * L) / 256, 256>>>(sq, cq, ir, wr, uir, out);
    prep_A_kernel<<<256, 256>>>(Hagg);
    gemm_qkv_kernel<<<dim3(32, 16, 3), 256>>>(Wq, Wk, Wv);
    attn_kernel<<<dim3(16, H), 256, ATTN_SMEM>>>();
    gemm_out_tc<<<64, 256>>>(out);
}

// round 11
// speedup vs baseline: 1.3104x; 1.1309x over previous
#include <cuda_runtime.h>
#include <cuda_bf16.h>
#include <math.h>
#include <stdint.h>

#define E 128
#define H 8
#define L 2048
#define HE 1024
#define HEL (HE * L)
#define NITEMS 50000
#define WAMT 5
#define SCALE_F 0.08838834764831845f

__device__ __nv_bfloat16 g_Ih[L * E], g_Il[L * E];           // I [l][e]
__device__ __nv_bfloat16 g_Wh[3 * HE * E], g_Wl[3 * HE * E]; // W [z][he][k]
__device__ __nv_bfloat16 g_Qh[H * L * E], g_Ql[H * L * E];   // [h][l][e], pre-scaled
__device__ __nv_bfloat16 g_Kh[H * L * E], g_Kl[H * L * E];   // [h][l][e]
__device__ __nv_bfloat16 g_Vh[H * E * L], g_Vl[H * E * L];   // [h][e][l]
__device__ __nv_bfloat16 g_bh[L * HE], g_bl[L * HE];         // [l][he]
__device__ __nv_bfloat16 g_Ah[E * HE], g_Al[E * HE];         // [e_out][k]

__device__ __forceinline__ uint32_t smem_u32(const void* p) {
    return (uint32_t)__cvta_generic_to_shared(p);
}
__device__ __forceinline__ void ldsm4(uint32_t* r, uint32_t a) {
    asm volatile("ldmatrix.sync.aligned.m8n8.x4.shared.b16 {%0,%1,%2,%3}, [%4];"
                 : "=r"(r[0]), "=r"(r[1]), "=r"(r[2]), "=r"(r[3]) : "r"(a));
}
__device__ __forceinline__ void mma_bf16(float* c, const uint32_t* a, const uint32_t* b) {
    asm volatile("mma.sync.aligned.m16n8k16.row.col.f32.bf16.bf16.f32 "
                 "{%0,%1,%2,%3}, {%4,%5,%6,%7}, {%8,%9}, {%0,%1,%2,%3};"
                 : "+f"(c[0]), "+f"(c[1]), "+f"(c[2]), "+f"(c[3])
                 : "r"(a[0]), "r"(a[1]), "r"(a[2]), "r"(a[3]), "r"(b[0]), "r"(b[1]));
}
__device__ __forceinline__ void split2(float a, float b, __nv_bfloat162& h, __nv_bfloat162& l) {
    h = __floats2bfloat162_rn(a, b);
    float2 r = __bfloat1622float2(h);
    l = __floats2bfloat162_rn(a - r.x, b - r.y);
}
#define CPA16(dst, src) \
    asm volatile("cp.async.cg.shared.global [%0], [%1], 16;" :: "r"(dst), "l"(src) : "memory")
#define CPA_COMMIT() asm volatile("cp.async.commit_group;" ::: "memory")
#define CPA_WAIT(n)  asm volatile("cp.async.wait_group %0;" :: "n"(n) : "memory")

// ---------------------------------------------------------------------------
__global__ void build_I_kernel(const int* __restrict__ sq, const int* __restrict__ cq,
                               const float* __restrict__ ir, const float* __restrict__ wr,
                               const float* __restrict__ uir, float* __restrict__ out) {
    int idx = blockIdx.x * blockDim.x + threadIdx.x;   // idx = l*128 + e
    if (idx < E) out[idx] = uir[idx];
    if (idx >= E * L) return;
    int e = idx & 127, l = idx >> 7;
    float iq = ir[e * NITEMS + sq[l]];
    float val = iq + wr[e * WAMT + cq[l]];
    __nv_bfloat16 hv = __float2bfloat16(val);
    g_Ih[idx] = hv;                                    // [l][e] == idx
    g_Il[idx] = __float2bfloat16(val - __bfloat162float(hv));
    out[E * L + idx] = iq;
}

__global__ void prep_W_kernel(const float* __restrict__ Wq, const float* __restrict__ Wk,
                              const float* __restrict__ Wv) {
    int idx = blockIdx.x * blockDim.x + threadIdx.x;   // 0..196607, 2 floats each
    int z = idx >> 16;
    int off = (idx & 65535) * 2;
    const float* W = (z == 0) ? Wq : (z == 1 ? Wk : Wv);
    float2 f = *(const float2*)&W[off];
    __nv_bfloat162 hh, ll;
    split2(f.x, f.y, hh, ll);
    *(__nv_bfloat162*)&g_Wh[z * (HE * E) + off] = hh;
    *(__nv_bfloat162*)&g_Wl[z * (HE * E) + off] = ll;
}

__global__ void prep_A_kernel(const float* __restrict__ A) {
    int idx = blockIdx.x * blockDim.x + threadIdx.x;
    int i2 = idx * 2;
    float2 f = *(const float2*)&A[i2];
    __nv_bfloat162 hh, ll;
    split2(f.x, f.y, hh, ll);
    *(__nv_bfloat162*)&g_Ah[i2] = hh;
    *(__nv_bfloat162*)&g_Al[i2] = ll;
}

// ---------------------------------------------------------------------------
// QKV projection via mma.sync: C[he 1024][l 2048] = W[he][k128] @ I[l][k128]^T.
// Per CTA: M=128 (he), N=128 (l), K=128, 3-term compensated.
// z=0: Q -> [h][l][e] scaled; z=1: K -> [h][l][e]; z=2: V -> [h][e][l] direct.
// ---------------------------------------------------------------------------
#define QSTR 136
#define QA_H 0
#define QA_L 34816
#define QB_H 69632
#define QB_L 104448
#define QKV_SMEM 139264

__global__ __launch_bounds__(256) void gemm_qkv_tc() {
    extern __shared__ __align__(128) char smq[];
    const uint32_t sb = smem_u32(smq);
    const int t = threadIdx.x, w = t >> 5, ln = t & 31;
    const int z = blockIdx.z;
    const int bm = blockIdx.y * 128;   // he tile (h = blockIdx.y since E=128... careful: 1024/128=8 tiles, h = bm>>7)
    const int bn = blockIdx.x * 128;   // l tile
    const __nv_bfloat16* Wh = g_Wh + (size_t)z * (HE * E);
    const __nv_bfloat16* Wl = g_Wl + (size_t)z * (HE * E);

    // Load A (W): 128 rows x 16 uint4, hi+lo
#pragma unroll
    for (int r = 0; r < 8; ++r) {
        int id = t + r * 256, row = id >> 4, c16 = id & 15;
        *(uint4*)(smq + QA_H + row * 272 + c16 * 16) =
            *((const uint4*)(Wh + (size_t)(bm + row) * E) + c16);
        *(uint4*)(smq + QA_L + row * 272 + c16 * 16) =
            *((const uint4*)(Wl + (size_t)(bm + row) * E) + c16);
    }
    // Load B (I): 128 rows x 16 uint4, hi+lo
#pragma unroll
    for (int r = 0; r < 8; ++r) {
        int id = t + r * 256, row = id >> 4, c16 = id & 15;
        *(uint4*)(smq + QB_H + row * 272 + c16 * 16) =
            *((const uint4*)(g_Ih + (size_t)(bn + row) * E) + c16);
        *(uint4*)(smq + QB_L + row * 272 + c16 * 16) =
            *((const uint4*)(g_Il + (size_t)(bn + row) * E) + c16);
    }
    __syncthreads();

    const int mbase = w * 16;
    const int mA = ln >> 3, g8 = ln & 7;
    const int aRow = mbase + g8 + (mA & 1) * 8;
    const int aCol = (mA >> 1) * 8;
    const int bRow = g8 + (mA >> 1) * 8;
    const int bCol = (mA & 1) * 8;

    float acc[16][4];
#pragma unroll
    for (int u = 0; u < 16; u++)
#pragma unroll
        for (int v = 0; v < 4; v++) acc[u][v] = 0.f;

#pragma unroll
    for (int ks = 0; ks < 8; ++ks) {
        int ko = ks * 16;
        uint32_t ah[4], al[4];
        uint32_t aoff = (uint32_t)((aRow * QSTR + ko + aCol) * 2);
        ldsm4(ah, sb + QA_H + aoff);
        ldsm4(al, sb + QA_L + aoff);
#pragma unroll
        for (int nb = 0; nb < 8; ++nb) {
            uint32_t bh[4], bl[4];
            uint32_t boff = (uint32_t)(((nb * 16 + bRow) * QSTR + ko + bCol) * 2);
            ldsm4(bh, sb + QB_H + boff);
            ldsm4(bl, sb + QB_L + boff);
            mma_bf16(acc[nb * 2], ah, bh);
            mma_bf16(acc[nb * 2], ah, bl);
            mma_bf16(acc[nb * 2], al, bh);
            mma_bf16(acc[nb * 2 + 1], ah, bh + 2);
            mma_bf16(acc[nb * 2 + 1], ah, bl + 2);
            mma_bf16(acc[nb * 2 + 1], al, bh + 2);
        }
    }

    const int g = ln >> 2, q2 = (ln & 3) * 2;
    if (z == 2) {
        // V: direct store [he][l], n (=l) contiguous
        const int row0 = bm + mbase + g;
#pragma unroll
        for (int nf = 0; nf < 16; ++nf) {
            int col = bn + nf * 8 + q2;
            __nv_bfloat162 h01, l01, h23, l23;
            split2(acc[nf][0], acc[nf][1], h01, l01);
            split2(acc[nf][2], acc[nf][3], h23, l23);
            *(__nv_bfloat162*)&g_Vh[(size_t)row0 * L + col] = h01;
            *(__nv_bfloat162*)&g_Vl[(size_t)row0 * L + col] = l01;
            *(__nv_bfloat162*)&g_Vh[(size_t)(row0 + 8) * L + col] = h23;
            *(__nv_bfloat162*)&g_Vl[(size_t)(row0 + 8) * L + col] = l23;
        }
    } else {
        // Q/K: transpose via fp32 staging aliased onto B region, then [h][l][e]
        __syncthreads();   // all warps done reading B smem
        float* st = (float*)(smq + QB_H);   // [128 l][132]
        const int r0 = mbase + g;
#pragma unroll
        for (int nf = 0; nf < 16; ++nf) {
            int lc = nf * 8 + q2;
            st[lc * 132 + r0]           = acc[nf][0];
            st[(lc + 1) * 132 + r0]     = acc[nf][1];
            st[lc * 132 + r0 + 8]       = acc[nf][2];
            st[(lc + 1) * 132 + r0 + 8] = acc[nf][3];
        }
        __syncthreads();
        const float s = (z == 0) ? SCALE_F : 1.0f;
        __nv_bfloat16* Dh = (z == 0) ? g_Qh : g_Kh;
        __nv_bfloat16* Dl = (z == 0) ? g_Ql : g_Kl;
        const int lrow = t >> 1, ec = (t & 1) * 64;
        const int h = bm >> 7;
        size_t base = ((size_t)h * L + bn + lrow) * E + ec;
#pragma unroll
        for (int i4 = 0; i4 < 16; ++i4) {
            float4 f = *(const float4*)&st[lrow * 132 + ec + i4 * 4];
            __nv_bfloat162 h01, l01, h23, l23;
            split2(f.x * s, f.y * s, h01, l01);
            split2(f.z * s, f.w * s, h23, l23);
            *(__nv_bfloat162*)&Dh[base + i4 * 4]     = h01;
            *(__nv_bfloat162*)&Dl[base + i4 * 4]     = l01;
            *(__nv_bfloat162*)&Dh[base + i4 * 4 + 2] = h23;
            *(__nv_bfloat162*)&Dl[base + i4 * 4 + 2] = l23;
        }
    }
}

// ---------------------------------------------------------------------------
// Flash attention, register-resident P (round-10, unchanged).
// ---------------------------------------------------------------------------
#define SQK 136
#define SV 72
#define S_QH 0
#define S_QL 17408
#define S_KV 34816
#define KSZ  17408
#define VSZ  18432
#define BUFSZ (2 * KSZ + 2 * VSZ)
#define S_XB (S_KV + BUFSZ)
#define ATTN_SMEM (S_KV + 2 * BUFSZ)

__device__ __forceinline__ void prefetch_kv(uint32_t sb, int buf,
                                            const __nv_bfloat16* Kh, const __nv_bfloat16* Kl,
                                            const __nv_bfloat16* Vh, const __nv_bfloat16* Vl,
                                            int ib, int t) {
    const uint32_t kb = sb + S_KV + buf * BUFSZ;
#pragma unroll
    for (int r = 0; r < 4; ++r) {
        int id = t + r * 256, row = id >> 4, c16 = id & 15;
        const char* sh = (const char*)(Kh + (size_t)(ib * 64 + row) * E) + c16 * 16;
        const char* sl = (const char*)(Kl + (size_t)(ib * 64 + row) * E) + c16 * 16;
        CPA16(kb + row * 272 + c16 * 16, sh);
        CPA16(kb + KSZ + row * 272 + c16 * 16, sl);
    }
    const uint32_t vb = kb + 2 * KSZ;
#pragma unroll
    for (int r = 0; r < 4; ++r) {
        int id = t + r * 256, row = id >> 3, c8 = id & 7;
        const char* sh = (const char*)(Vh + (size_t)row * L + ib * 64) + c8 * 16;
        const char* sl = (const char*)(Vl + (size_t)row * L + ib * 64) + c8 * 16;
        CPA16(vb + row * 144 + c8 * 16, sh);
        CPA16(vb + VSZ + row * 144 + c8 * 16, sl);
    }
    CPA_COMMIT();
}

__global__ __launch_bounds__(256, 1) void attn_kernel() {
    extern __shared__ __align__(128) char smc[];
    const uint32_t sb = smem_u32(smc);
    const int t = threadIdx.x, w = t >> 5, ln = t & 31;
    const int h = blockIdx.y, px = blockIdx.x;

    const __nv_bfloat16* Qh = g_Qh + (size_t)h * L * E;
    const __nv_bfloat16* Ql = g_Ql + (size_t)h * L * E;
    const __nv_bfloat16* Kh = g_Kh + (size_t)h * L * E;
    const __nv_bfloat16* Kl = g_Kl + (size_t)h * L * E;
    const __nv_bfloat16* Vh = g_Vh + (size_t)h * E * L;
    const __nv_bfloat16* Vl = g_Vl + (size_t)h * E * L;

    const int jw  = (w >> 1) * 16;
    const int ihw = (w & 1) * 32;
    const int g   = ln >> 2;
    const int q2  = (ln & 3) * 2;
    const int mA = ln >> 3, g8 = ln & 7;
    const int aRow = jw + g8 + (mA & 1) * 8;
    const int aCol = (mA >> 1) * 8;
    const int bRow = g8 + (mA >> 1) * 8;
    const int bCol = (mA & 1) * 8;

#pragma unroll 1
    for (int ts = 0; ts < 2; ++ts) {
        const int jt = ts ? px : (31 - px);
        const int qb = jt << 6;
        __syncthreads();

        prefetch_kv(sb, 0, Kh, Kl, Vh, Vl, 0, t);

#pragma unroll
        for (int r = 0; r < 4; ++r) {
            int id = t + r * 256, row = id >> 4, c16 = id & 15;
            *(uint4*)(smc + S_QH + row * 272 + c16 * 16) =
                *((const uint4*)(Qh + (size_t)(qb + row) * E) + c16);
            *(uint4*)(smc + S_QL + row * 272 + c16 * 16) =
                *((const uint4*)(Ql + (size_t)(qb + row) * E) + c16);
        }

        float bacc[16][4];
#pragma unroll
        for (int u = 0; u < 16; u++)
#pragma unroll
            for (int v = 0; v < 4; v++) bacc[u][v] = 0.f;
        float lsum0 = 0.f, lsum1 = 0.f;
        const int jg0 = qb + jw + g, jg1 = jg0 + 8;

#pragma unroll 1
        for (int ib = 0; ib <= jt; ++ib) {
            __syncthreads();
            if (ib < jt) {
                prefetch_kv(sb, (ib + 1) & 1, Kh, Kl, Vh, Vl, ib + 1, t);
                CPA_WAIT(1);
            } else {
                CPA_WAIT(0);
            }
            __syncthreads();

            const uint32_t kH = sb + S_KV + (ib & 1) * BUFSZ;
            const uint32_t kL = kH + KSZ;
            const uint32_t vH = kH + 2 * KSZ;
            const uint32_t vL = vH + VSZ;

            float sacc[4][4];
#pragma unroll
            for (int u = 0; u < 4; u++)
#pragma unroll
                for (int v = 0; v < 4; v++) sacc[u][v] = 0.f;
#pragma unroll
            for (int ks = 0; ks < 8; ++ks) {
                int e0 = ks * 16;
                uint32_t ah[4], al[4];
                ldsm4(ah, sb + S_QH + (uint32_t)((aRow * SQK + e0 + aCol) * 2));
                ldsm4(al, sb + S_QL + (uint32_t)((aRow * SQK + e0 + aCol) * 2));
#pragma unroll
                for (int it = 0; it < 2; ++it) {
                    uint32_t bh[4], bl[4];
                    uint32_t boff = (uint32_t)(((ihw + it * 16 + bRow) * SQK + e0 + bCol) * 2);
                    ldsm4(bh, kH + boff);
                    ldsm4(bl, kL + boff);
                    mma_bf16(sacc[it * 2], ah, bh);
                    mma_bf16(sacc[it * 2], ah, bl);
                    mma_bf16(sacc[it * 2], al, bh);
                    mma_bf16(sacc[it * 2 + 1], ah, bh + 2);
                    mma_bf16(sacc[it * 2 + 1], ah, bl + 2);
                    mma_bf16(sacc[it * 2 + 1], al, bh + 2);
                }
            }

            uint32_t aPh[2][4], aPl[2][4];
#pragma unroll
            for (int nf = 0; nf < 4; ++nf) {
                int ig = ib * 64 + ihw + nf * 8 + q2;
                float p0 = (ig     <= jg0) ? __expf(sacc[nf][0]) : 0.f;
                float p1 = (ig + 1 <= jg0) ? __expf(sacc[nf][1]) : 0.f;
                float p2 = (ig     <= jg1) ? __expf(sacc[nf][2]) : 0.f;
                float p3 = (ig + 1 <= jg1) ? __expf(sacc[nf][3]) : 0.f;
                lsum0 += p0 + p1;
                lsum1 += p2 + p3;
                __nv_bfloat162 h01, l01, h23, l23;
                split2(p0, p1, h01, l01);
                split2(p2, p3, h23, l23);
                int kb = nf >> 1, sub = (nf & 1) * 2;
                aPh[kb][sub]     = *(uint32_t*)&h01;
                aPh[kb][sub + 1] = *(uint32_t*)&h23;
                aPl[kb][sub]     = *(uint32_t*)&l01;
                aPl[kb][sub + 1] = *(uint32_t*)&l23;
            }

#pragma unroll
            for (int kb = 0; kb < 2; ++kb) {
#pragma unroll
                for (int ef = 0; ef < 8; ++ef) {
                    uint32_t bh[4], bl[4];
                    uint32_t boff = (uint32_t)(((ef * 16 + bRow) * SV +
                                                ihw + kb * 16 + bCol) * 2);
                    ldsm4(bh, vH + boff);
                    ldsm4(bl, vL + boff);
                    mma_bf16(bacc[ef * 2], aPh[kb], bh);
                    mma_bf16(bacc[ef * 2], aPh[kb], bl);
                    mma_bf16(bacc[ef * 2], aPl[kb], bh);
                    mma_bf16(bacc[ef * 2 + 1], aPh[kb], bh + 2);
                    mma_bf16(bacc[ef * 2 + 1], aPh[kb], bl + 2);
                    mma_bf16(bacc[ef * 2 + 1], aPl[kb], bh + 2);
                }
            }
        }

        __syncthreads();
        float* XB = (float*)(smc + S_XB);
        const int xbase = ((w >> 1) * 32 + ln) * 68;
        if (w & 1) {
#pragma unroll
            for (int nf = 0; nf < 16; ++nf) {
                XB[xbase + nf * 4 + 0] = bacc[nf][0];
                XB[xbase + nf * 4 + 1] = bacc[nf][1];
                XB[xbase + nf * 4 + 2] = bacc[nf][2];
                XB[xbase + nf * 4 + 3] = bacc[nf][3];
            }
            XB[xbase + 64] = lsum0;
            XB[xbase + 65] = lsum1;
        }
        __syncthreads();
        if (!(w & 1)) {
#pragma unroll
            for (int nf = 0; nf < 16; ++nf) {
                bacc[nf][0] += XB[xbase + nf * 4 + 0];
                bacc[nf][1] += XB[xbase + nf * 4 + 1];
                bacc[nf][2] += XB[xbase + nf * 4 + 2];
                bacc[nf][3] += XB[xbase + nf * 4 + 3];
            }
            lsum0 += XB[xbase + 64];
            lsum1 += XB[xbase + 65];
            lsum0 += __shfl_xor_sync(0xffffffffu, lsum0, 1);
            lsum0 += __shfl_xor_sync(0xffffffffu, lsum0, 2);
            lsum1 += __shfl_xor_sync(0xffffffffu, lsum1, 1);
            lsum1 += __shfl_xor_sync(0xffffffffu, lsum1, 2);
            float li0 = 1.0f / lsum0, li1 = 1.0f / lsum1;
            const int j0 = qb + jw + g;
#pragma unroll
            for (int nf = 0; nf < 16; ++nf) {
                int e0 = h * E + nf * 8 + q2;
                __nv_bfloat162 h01, l01, h23, l23;
                split2(bacc[nf][0] * li0, bacc[nf][1] * li0, h01, l01);
                split2(bacc[nf][2] * li1, bacc[nf][3] * li1, h23, l23);
                size_t b0 = (size_t)j0 * HE + e0;
                size_t b1 = (size_t)(j0 + 8) * HE + e0;
                *(__nv_bfloat162*)&g_bh[b0] = h01;
                *(__nv_bfloat162*)&g_bl[b0] = l01;
                *(__nv_bfloat162*)&g_bh[b1] = h23;
                *(__nv_bfloat162*)&g_bl[b1] = l23;
            }
        }
    }
}

// ---------------------------------------------------------------------------
#define O_AH 0
#define O_AL 18432
#define O_BH 36864
#define O_BL 41472

__global__ __launch_bounds__(256) void gemm_out_tc(float* __restrict__ out) {
    __shared__ __align__(16) char sm2[46080];
    const uint32_t sb = smem_u32(sm2);
    const int t = threadIdx.x, w = t >> 5, ln = t & 31;
    const int bn = blockIdx.x * 32;
    const int mbase = w * 16;
    const int mA = ln >> 3, g8 = ln & 7;
    const int aRow = mbase + g8 + (mA & 1) * 8;
    const int aCol = (mA >> 1) * 8;
    const int bRow = g8 + (mA >> 1) * 8;
    const int bCol = (mA & 1) * 8;

    float acc[4][4];
#pragma unroll
    for (int u = 0; u < 4; u++)
#pragma unroll
        for (int v = 0; v < 4; v++) acc[u][v] = 0.f;

    for (int kc = 0; kc < 16; ++kc) {
        const int k0 = kc * 64;
        __syncthreads();
#pragma unroll
        for (int r = 0; r < 4; ++r) {
            int id = t + r * 256, row = id >> 3, c8 = id & 7;
            *(uint4*)(sm2 + O_AH + row * 144 + c8 * 16) =
                *((const uint4*)(g_Ah + (size_t)row * HE + k0) + c8);
            *(uint4*)(sm2 + O_AL + row * 144 + c8 * 16) =
                *((const uint4*)(g_Al + (size_t)row * HE + k0) + c8);
        }
        {
            int row = t >> 3, c8 = t & 7;
            *(uint4*)(sm2 + O_BH + row * 144 + c8 * 16) =
                *((const uint4*)(g_bh + (size_t)(bn + row) * HE + k0) + c8);
            *(uint4*)(sm2 + O_BL + row * 144 + c8 * 16) =
                *((const uint4*)(g_bl + (size_t)(bn + row) * HE + k0) + c8);
        }
        __syncthreads();
#pragma unroll
        for (int kf = 0; kf < 4; ++kf) {
            int ko = kf * 16;
            uint32_t ah[4], al[4];
            uint32_t aoff = (uint32_t)((aRow * 72 + ko + aCol) * 2);
            ldsm4(ah, sb + O_AH + aoff);
            ldsm4(al, sb + O_AL + aoff);
#pragma unroll
            for (int np = 0; np < 2; ++np) {
                int n16 = np * 16;
                uint32_t bh[4], bl[4];
                uint32_t boff = (uint32_t)(((n16 + bRow) * 72 + ko + bCol) * 2);
                ldsm4(bh, sb + O_BH + boff);
                ldsm4(bl, sb + O_BL + boff);
                mma_bf16(acc[np * 2], ah, bh);
                mma_bf16(acc[np * 2], ah, bl);
                mma_bf16(acc[np * 2], al, bh);
                mma_bf16(acc[np * 2 + 1], ah, bh + 2);
                mma_bf16(acc[np * 2 + 1], ah, bl + 2);
                mma_bf16(acc[np * 2 + 1], al, bh + 2);
            }
        }
    }
    const int r0 = mbase + (ln >> 2);
#pragma unroll
    for (int nf = 0; nf < 4; ++nf) {
        int j0 = bn + nf * 8 + (ln & 3) * 2;
        int ee[4] = {r0, r0, r0 + 8, r0 + 8};
        int jj[4] = {j0, j0 + 1, j0, j0 + 1};
#pragma unroll
        for (int q = 0; q < 4; ++q) {
            int dst = (jj[q] < L - 1) ? (E + jj[q] * E + ee[q]) : (2 * E * L + ee[q]);
            out[dst] = acc[nf][q];
        }
    }
}

// ---------------------------------------------------------------------------
extern "C" void kernel_launch(void* const* d_in, const int* in_sizes, int n_in,
                              void* d_out, int out_size) {
    const int* sq = (const int*)d_in[0];
    const int* cq = (const int*)d_in[1];
    const float* ir = (const float*)d_in[2];
    const float* uir = (const float*)d_in[3];
    const float* wr = (const float*)d_in[4];
    const float* Wq = (const float*)d_in[5];
    const float* Wk = (const float*)d_in[6];
    const float* Wv = (const float*)d_in[7];
    const float* Hagg = (const float*)d_in[8];
    float* out = (float*)d_out;
    cudaFuncSetAttribute(attn_kernel, cudaFuncAttributeMaxDynamicSharedMemorySize, ATTN_SMEM);
    cudaFuncSetAttribute(gemm_qkv_tc, cudaFuncAttributeMaxDynamicSharedMemorySize, QKV_SMEM);
    build_I_kernel<<<(E * L) / 256, 256>>>(sq, cq, ir, wr, uir, out);
    prep_W_kernel<<<768, 256>>>(Wq, Wk, Wv);
    prep_A_kernel<<<256, 256>>>(Hagg);
    gemm_qkv_tc<<<dim3(16, 8, 3), 256, QKV_SMEM>>>();
    attn_kernel<<<dim3(16, H), 256, ATTN_SMEM>>>();
    gemm_out_tc<<<64, 256>>>(out);
}